// round 1
// baseline (speedup 1.0000x reference)
#include <cuda_runtime.h>
#include <cstdint>

// Problem constants
#define C_IN   8
#define H_IN   32
#define W_IN   32
#define C_OUT  32
#define KSZ    4
#define STRIDE 2
#define PAD    1
#define HO     16
#define WO     16
#define IN_FEAT  (C_IN * H_IN * W_IN)     // 8192
#define OUT_FEAT (C_OUT * HO * WO)        // 8192
#define WMAT_ELEMS ((unsigned)OUT_FEAT * (unsigned)IN_FEAT)  // 67,108,864

// Output layout in d_out (float32):
//   [0            : 16384)                    out_bounds  (lower 8192, upper 8192)
//   [16384        : 16384 + 67108864)         W_mat [OUT_FEAT, IN_FEAT] row-major
//   [16384+67108864 : +8192)                  bias_backsub
#define OFF_WMAT  16384u
#define OFF_BIASB (16384u + WMAT_ELEMS)

// ---------------------------------------------------------------------------
// Kernel 1: interval conv bounds + bias_backsub.
// One thread per output position r = co*256 + ho*16 + wo (8192 threads).
// out_bounds[0] = conv(W+, l) + conv(W-, u) + bias  (lower)
// out_bounds[1] = conv(W+, u) + conv(W-, l) + bias  (upper)
// The back-substituted bounds are mathematically identical, so the reference's
// tighten step is a no-op — we emit the conv result for both.
// ---------------------------------------------------------------------------
__global__ void bounds_kernel(const float* __restrict__ bounds,
                              const float* __restrict__ weight,
                              const float* __restrict__ bias,
                              float* __restrict__ out) {
    int r = blockIdx.x * blockDim.x + threadIdx.x;
    if (r >= OUT_FEAT) return;
    int co = r >> 8;
    int ho = (r >> 4) & 15;
    int wo = r & 15;

    const float* l = bounds;              // [8,32,32]
    const float* u = bounds + IN_FEAT;    // [8,32,32]

    int h0 = ho * STRIDE - PAD;
    int w0 = wo * STRIDE - PAD;

    float lo = 0.0f, up = 0.0f;
#pragma unroll
    for (int ci = 0; ci < C_IN; ci++) {
#pragma unroll
        for (int kh = 0; kh < KSZ; kh++) {
            int h = h0 + kh;
            if ((unsigned)h >= (unsigned)H_IN) continue;
#pragma unroll
            for (int kw = 0; kw < KSZ; kw++) {
                int w = w0 + kw;
                if ((unsigned)w >= (unsigned)W_IN) continue;
                float wt = __ldg(weight + (((co * C_IN + ci) * KSZ + kh) * KSZ + kw));
                int in_idx = (ci * H_IN + h) * W_IN + w;
                float lv = __ldg(l + in_idx);
                float uv = __ldg(u + in_idx);
                float wp = fmaxf(wt, 0.0f);
                float wm = fminf(wt, 0.0f);
                lo = fmaf(wp, lv, fmaf(wm, uv, lo));
                up = fmaf(wp, uv, fmaf(wm, lv, up));
            }
        }
    }
    float b = __ldg(bias + co);
    out[r]            = lo + b;   // lower
    out[OUT_FEAT + r] = up + b;   // upper
    out[OFF_BIASB + r] = b;       // bias_backsub (repeat_interleave over 256)
}

// ---------------------------------------------------------------------------
// Kernel 2: materialize the Toeplitz matrix W_mat [8192 x 8192].
// W_mat[r, c] = weight[co, ci, kh, kw] if kh = h - (2*ho - 1) in [0,4)
//                                      and kw = w - (2*wo - 1) in [0,4)
//               else 0.
// Pure streaming store: one float4 per thread, __stcs to bypass L2 retention
// (268 MB >> 126 MB L2). Index math per 16B store is ~a dozen ALU ops, fully
// hidden under the store stream.
// c is aligned to 4 within a row (8192 % 4 == 0) and w-groups of 4 never
// straddle an h boundary (w0 in {0,4,...,28}).
// ---------------------------------------------------------------------------
__global__ void wmat_kernel(const float* __restrict__ weight,
                            float* __restrict__ wmat) {
    unsigned idx4 = blockIdx.x * blockDim.x + threadIdx.x;  // float4 index, < 2^24
    unsigned e = idx4 << 2;          // element index
    unsigned r = e >> 13;            // row = e / 8192
    unsigned c = e & 8191u;          // col

    int co = r >> 8;
    int ho = (r >> 4) & 15;
    int wo = r & 15;

    int ci = c >> 10;
    unsigned rem = c & 1023u;
    int h = rem >> 5;
    int w = rem & 31;

    int kh = h - (ho * STRIDE - PAD);
    float4 v = make_float4(0.0f, 0.0f, 0.0f, 0.0f);
    if ((unsigned)kh < (unsigned)KSZ) {
        int kw0 = w - (wo * STRIDE - PAD);
        const float* wrow = weight + (((co * C_IN + ci) * KSZ + kh) * KSZ);
        float t[4];
#pragma unroll
        for (int j = 0; j < 4; j++) {
            int kw = kw0 + j;
            t[j] = ((unsigned)kw < (unsigned)KSZ) ? __ldg(wrow + kw) : 0.0f;
        }
        v = make_float4(t[0], t[1], t[2], t[3]);
    }
    __stcs(reinterpret_cast<float4*>(wmat) + idx4, v);
}

// ---------------------------------------------------------------------------
extern "C" void kernel_launch(void* const* d_in, const int* in_sizes, int n_in,
                              void* d_out, int out_size) {
    const float* bounds = (const float*)d_in[0];  // [2,8,32,32]  16384
    const float* weight = (const float*)d_in[1];  // [32,8,4,4]   4096
    const float* bias   = (const float*)d_in[2];  // [32]
    // d_in[3] = assignment, unused by the computation.
    float* out = (float*)d_out;

    // Big streaming kernel: 67,108,864 / 4 = 16,777,216 float4 stores.
    {
        const int threads = 256;
        const int blocks = (int)(WMAT_ELEMS / 4u / (unsigned)threads);  // 65536
        wmat_kernel<<<blocks, threads>>>(weight, out + OFF_WMAT);
    }
    // Small kernel: bounds + bias_backsub (8192 threads).
    {
        const int threads = 256;
        const int blocks = (OUT_FEAT + threads - 1) / threads;  // 32
        bounds_kernel<<<blocks, threads>>>(bounds, weight, bias, out);
    }
}

// round 2
// speedup vs baseline: 1.1297x; 1.1297x over previous
#include <cuda_runtime.h>
#include <cstdint>

// Problem constants
#define C_IN   8
#define H_IN   32
#define W_IN   32
#define C_OUT  32
#define KSZ    4
#define STRIDE 2
#define PAD    1
#define HO     16
#define WO     16
#define IN_FEAT  (C_IN * H_IN * W_IN)     // 8192
#define OUT_FEAT (C_OUT * HO * WO)        // 8192
#define WMAT_ELEMS ((unsigned)OUT_FEAT * (unsigned)IN_FEAT)  // 67,108,864

// Output layout in d_out (float32):
//   [0 : 16384)                       out_bounds (lower 8192, upper 8192)
//   [16384 : 16384+67108864)          W_mat [OUT_FEAT, IN_FEAT] row-major
//   [16384+67108864 : +8192)          bias_backsub
#define OFF_WMAT  16384u
#define OFF_BIASB (16384u + WMAT_ELEMS)

// Grid layout of the fused kernel:
//   blocks [0, BOUNDS_BLOCKS)             : interval-conv bounds (1 warp per r)
//   blocks [BOUNDS_BLOCKS, +WMAT_BLOCKS)  : Toeplitz streaming stores
#define BOUNDS_BLOCKS 1024
#define WMAT_BLOCKS   65536   // 65536 * 256 threads * 1 float4 = 67,108,864 elems

__global__ void __launch_bounds__(256) fused_kernel(
        const float* __restrict__ bounds,
        const float* __restrict__ weight,
        const float* __restrict__ bias,
        float* __restrict__ out) {
    unsigned bid = blockIdx.x;

    if (bid >= BOUNDS_BLOCKS) {
        // ------------------------------------------------------------------
        // Toeplitz matrix: W_mat[r,c] = weight[co,ci,kh,kw] where
        //   kh = h - (2*ho - 1), kw = w - (2*wo - 1), valid if in [0,4);
        // else 0. One float4 streaming store per thread (__stcs: 268 MB >> L2).
        // ------------------------------------------------------------------
        unsigned idx4 = (bid - BOUNDS_BLOCKS) * 256u + threadIdx.x; // < 2^24
        unsigned e = idx4 << 2;          // element index
        unsigned r = e >> 13;            // row
        unsigned c = e & 8191u;          // col

        int co = r >> 8;
        int ho = (r >> 4) & 15;
        int wo = r & 15;

        int ci = c >> 10;
        unsigned rem = c & 1023u;
        int h = rem >> 5;
        int w = rem & 31;

        int kh = h - (ho * STRIDE - PAD);
        float4 v = make_float4(0.0f, 0.0f, 0.0f, 0.0f);
        if ((unsigned)kh < (unsigned)KSZ) {
            int kw0 = w - (wo * STRIDE - PAD);
            const float* wrow = weight + (((co * C_IN + ci) * KSZ + kh) * KSZ);
            float t[4];
#pragma unroll
            for (int j = 0; j < 4; j++) {
                int kw = kw0 + j;
                t[j] = ((unsigned)kw < (unsigned)KSZ) ? __ldg(wrow + kw) : 0.0f;
            }
            v = make_float4(t[0], t[1], t[2], t[3]);
        }
        __stcs(reinterpret_cast<float4*>(out + OFF_WMAT) + idx4, v);
        return;
    }

    // ----------------------------------------------------------------------
    // Interval conv bounds + bias_backsub. One WARP per output r.
    // Lane l accumulates taps t = l, l+32, l+64, l+96 of the 128 (ci,kh,kw)
    // taps, then butterfly-reduces. Back-substituted bounds are
    // mathematically identical to these, so the tighten step is a no-op.
    // ----------------------------------------------------------------------
    int warp = threadIdx.x >> 5;
    int lane = threadIdx.x & 31;
    int r = bid * 8 + warp;              // 1024 blocks * 8 warps = 8192 outputs

    int co = r >> 8;
    int ho = (r >> 4) & 15;
    int wo = r & 15;
    int h0 = ho * STRIDE - PAD;
    int w0 = wo * STRIDE - PAD;

    const float* l = bounds;             // [8,32,32]
    const float* u = bounds + IN_FEAT;

    float lo = 0.0f, up = 0.0f;
#pragma unroll
    for (int j = 0; j < 4; j++) {
        int t = lane + j * 32;           // tap index: ci*16 + kh*4 + kw
        int ci = t >> 4;
        int kh = (t >> 2) & 3;
        int kw = t & 3;
        int h = h0 + kh;
        int w = w0 + kw;
        if ((unsigned)h < (unsigned)H_IN && (unsigned)w < (unsigned)W_IN) {
            float wt = __ldg(weight + (((co * C_IN + ci) * KSZ + kh) * KSZ + kw));
            int in_idx = (ci * H_IN + h) * W_IN + w;
            float lv = __ldg(l + in_idx);
            float uv = __ldg(u + in_idx);
            float wp = fmaxf(wt, 0.0f);
            float wm = fminf(wt, 0.0f);
            lo = fmaf(wp, lv, fmaf(wm, uv, lo));
            up = fmaf(wp, uv, fmaf(wm, lv, up));
        }
    }
#pragma unroll
    for (int off = 16; off > 0; off >>= 1) {
        lo += __shfl_xor_sync(0xFFFFFFFFu, lo, off);
        up += __shfl_xor_sync(0xFFFFFFFFu, up, off);
    }
    if (lane == 0) {
        float b = __ldg(bias + co);
        out[r]             = lo + b;     // lower
        out[OUT_FEAT + r]  = up + b;     // upper
        out[OFF_BIASB + r] = b;          // bias_backsub
    }
}

extern "C" void kernel_launch(void* const* d_in, const int* in_sizes, int n_in,
                              void* d_out, int out_size) {
    const float* bounds = (const float*)d_in[0];  // [2,8,32,32]
    const float* weight = (const float*)d_in[1];  // [32,8,4,4]
    const float* bias   = (const float*)d_in[2];  // [32]
    // d_in[3] = assignment, unused.
    float* out = (float*)d_out;

    fused_kernel<<<BOUNDS_BLOCKS + WMAT_BLOCKS, 256>>>(bounds, weight, bias, out);
}